// round 6
// baseline (speedup 1.0000x reference)
#include <cuda_runtime.h>
#include <cuda_fp16.h>
#include <cstdint>

#define N_TEMPL 4
#define N_RES   768
#define NCH     64
#define NGCOLS  62    // gather cols: 0..38 bins, 39 zero, 40..61 aa_j
#define JSPLIT  2
#define JCHUNK  (N_RES / JSPLIT)   // 384

// smem: Wt_h 62*64*2 = 7936 B + sData 384*16 = 6144 B + consts ≈ 14.2 KB
__global__ __launch_bounds__(256) void tpe_kernel(
    const float* __restrict__ pos,      // [T,768,37,3]
    const float* __restrict__ pb,       // [T,768,3]
    const float* __restrict__ pbm,      // [T,768]
    const float* __restrict__ aam,      // [T,768,37]
    const int*   __restrict__ aatype,   // [T,768]
    const float* __restrict__ lw,       // [64,88] row-major (o-major)
    const float* __restrict__ lb,       // [64]
    float* __restrict__ out)            // [T,768,768,64]
{
    __shared__ alignas(16) __half Wt_h[NGCOLS * NCH];
    __shared__ float4 sData[JCHUNK];  // uvx, uvy, uvz, packed(bin | aaCol<<6 | pb<<12 | fm<<13)
    __shared__ float  sM[9];
    __shared__ float  sCa[3];
    __shared__ float  sPb[3];
    __shared__ float  sPbmI;
    __shared__ float  sFmI;
    __shared__ int    sAaI;

    const float EPS = 1e-6f;
    const int row  = blockIdx.x >> 1;          // (t, i)
    const int half = blockIdx.x & 1;
    const int t = row / N_RES;
    const int i = row % N_RES;
    const int j0 = half * JCHUNK;
    const int tid = threadIdx.x;

    // ---- Phase 0: stage fp16 gather table (transposed) + build rigid frame ----
    for (int idx = tid; idx < NGCOLS * NCH; idx += 256) {
        int c = idx >> 6, o = idx & 63;
        float v = (c == 39) ? 0.0f : lw[o * 88 + c];
        Wt_h[idx] = __float2half_rn(v);
    }

    if (tid == 0) {
        const float* pr = pos + ((size_t)(t * N_RES + i) * 37) * 3;
        float nx0 = pr[0], nx1 = pr[1], nx2 = pr[2];     // N
        float ca0 = pr[3], ca1 = pr[4], ca2 = pr[5];     // CA
        float cc0 = pr[6], cc1 = pr[7], cc2 = pr[8];     // C
        float n0 = nx0 - ca0, n1 = nx1 - ca1, n2 = nx2 - ca2;
        float c0 = cc0 - ca0, c1v = cc1 - ca1, c2v = cc2 - ca2;

        float d2xy = c0 * c0 + c1v * c1v;
        float norm1 = sqrtf(EPS + d2xy);
        float s1 = -c1v / norm1, co1 = c0 / norm1;
        float norm2 = sqrtf(EPS + d2xy + c2v * c2v);
        float s2 = c2v / norm2, co2 = sqrtf(d2xy) / norm2;

        float r00 = co2 * co1, r01 = -co2 * s1, r02 = s2;
        float r10 = s1,        r11 = co1,       r12 = 0.0f;
        float r20 = -s2 * co1, r21 = s2 * s1,   r22 = co2;

        float nyp = r10 * n0 + r11 * n1 + r12 * n2;
        float nzp = r20 * n0 + r21 * n1 + r22 * n2;
        float norm3 = sqrtf(EPS + nyp * nyp + nzp * nzp);
        float sn = -nzp / norm3, cn = nyp / norm3;

        sM[0] = r00; sM[1] = r01; sM[2] = r02;
        sM[3] = cn * r10 - sn * r20; sM[4] = cn * r11 - sn * r21; sM[5] = cn * r12 - sn * r22;
        sM[6] = sn * r10 + cn * r20; sM[7] = sn * r11 + cn * r21; sM[8] = sn * r12 + cn * r22;

        sCa[0] = ca0; sCa[1] = ca1; sCa[2] = ca2;
        const float* pbi = pb + (size_t)(t * N_RES + i) * 3;
        sPb[0] = pbi[0]; sPb[1] = pbi[1]; sPb[2] = pbi[2];
        sPbmI = pbm[t * N_RES + i];
        const float* ami = aam + (size_t)(t * N_RES + i) * 37;
        sFmI = ami[0] * ami[1] * ami[2];
        sAaI = aatype[t * N_RES + i];
    }
    __syncthreads();

    // ---------------- Phase 1: per-j scalars for this CTA's j-chunk -----------
    {
        const float m0 = sM[0], m1 = sM[1], m2 = sM[2];
        const float m3 = sM[3], m4 = sM[4], m5 = sM[5];
        const float m6 = sM[6], m7 = sM[7], m8 = sM[8];
        const float cai0 = sCa[0], cai1 = sCa[1], cai2 = sCa[2];
        const float pbi0 = sPb[0], pbi1 = sPb[1], pbi2 = sPb[2];
        const float pbmi = sPbmI, fmi = sFmI;

        for (int jl = tid; jl < JCHUNK; jl += 256) {
            int j = j0 + jl;
            // distogram bin (match reference FP ordering)
            const float* pbj = pb + (size_t)(t * N_RES + j) * 3;
            float dx = __fadd_rn(pbi0, -pbj[0]);
            float dy = __fadd_rn(pbi1, -pbj[1]);
            float dz = __fadd_rn(pbi2, -pbj[2]);
            float dsq = __fadd_rn(__fadd_rn(__fmul_rn(dx, dx), __fmul_rn(dy, dy)),
                                  __fmul_rn(dz, dz));
            int k = (int)floorf((sqrtf(dsq) - 3.25f) * 0.8f);
            k = min(max(k, -1), 38);
            int bin = -1;
            int clo = max(k - 1, 0), chi = min(k + 1, 38);
            #pragma unroll
            for (int c = 0; c < 3; ++c) {
                int cand = clo + c;
                if (cand > chi) break;
                float lbv = 3.25f + (float)cand * 1.25f;  lbv = lbv * lbv;
                float ubv = (cand == 38) ? 1e8f
                           : (3.25f + (float)(cand + 1) * 1.25f) *
                             (3.25f + (float)(cand + 1) * 1.25f);
                if (dsq > lbv && dsq < ubv) { bin = cand; break; }
            }

            // rigid vec + unit vector
            const float* pj = pos + ((size_t)(t * N_RES + j) * 37 + 1) * 3; // CA_j
            float ddx = pj[0] - cai0, ddy = pj[1] - cai1, ddz = pj[2] - cai2;
            float rvx = m0 * ddx + m1 * ddy + m2 * ddz;
            float rvy = m3 * ddx + m4 * ddy + m5 * ddz;
            float rvz = m6 * ddx + m7 * ddy + m8 * ddz;
            float inv = 1.0f / sqrtf(EPS + (rvx * rvx + rvy * rvy + rvz * rvz));
            float uvx = rvx * inv, uvy = rvy * inv, uvz = rvz * inv;

            const float* amj = aam + (size_t)(t * N_RES + j) * 37;
            float fm2 = fmi * (amj[0] * amj[1] * amj[2]);
            float pb2 = pbmi * pbm[t * N_RES + j];

            int binCol = (bin < 0) ? 39 : bin;
            int aaCol  = 40 + aatype[t * N_RES + j];
            int packed = binCol | (aaCol << 6);
            if (pb2 != 0.0f) packed |= 1 << 12;
            if (fm2 != 0.0f) packed |= 1 << 13;
            sData[jl] = make_float4(uvx, uvy, uvz, __int_as_float(packed));
        }
    }
    __syncthreads();

    // ---------------- Phase 2: 16 ch-threads, 2 j's in flight per thread ------
    const int oq = tid & 15;
    const int jl = tid >> 4;          // 0..15
    const int ob = oq * 4;

    float4 rowb, w39v, w84v, w85v, w86v, bv;
    {
        int ai = sAaI;
        rowb = make_float4(
            __ldg(&lw[(ob + 0) * 88 + 62 + ai]) + __ldg(&lw[(ob + 0) * 88 + 87]),
            __ldg(&lw[(ob + 1) * 88 + 62 + ai]) + __ldg(&lw[(ob + 1) * 88 + 87]),
            __ldg(&lw[(ob + 2) * 88 + 62 + ai]) + __ldg(&lw[(ob + 2) * 88 + 87]),
            __ldg(&lw[(ob + 3) * 88 + 62 + ai]) + __ldg(&lw[(ob + 3) * 88 + 87]));
        w39v = make_float4(__ldg(&lw[(ob + 0) * 88 + 39]), __ldg(&lw[(ob + 1) * 88 + 39]),
                           __ldg(&lw[(ob + 2) * 88 + 39]), __ldg(&lw[(ob + 3) * 88 + 39]));
        w84v = make_float4(__ldg(&lw[(ob + 0) * 88 + 84]), __ldg(&lw[(ob + 1) * 88 + 84]),
                           __ldg(&lw[(ob + 2) * 88 + 84]), __ldg(&lw[(ob + 3) * 88 + 84]));
        w85v = make_float4(__ldg(&lw[(ob + 0) * 88 + 85]), __ldg(&lw[(ob + 1) * 88 + 85]),
                           __ldg(&lw[(ob + 2) * 88 + 85]), __ldg(&lw[(ob + 3) * 88 + 85]));
        w86v = make_float4(__ldg(&lw[(ob + 0) * 88 + 86]), __ldg(&lw[(ob + 1) * 88 + 86]),
                           __ldg(&lw[(ob + 2) * 88 + 86]), __ldg(&lw[(ob + 3) * 88 + 86]));
        bv   = *(const float4*)&lb[ob];
    }

    float* orow = out + ((size_t)(t * N_RES + i) * N_RES + j0) * NCH;

    #pragma unroll 3
    for (int jb = 0; jb < JCHUNK; jb += 32) {
        int ja = jb + jl;
        int jc = ja + 16;

        // issue all loads up front: 2 broadcasts + 4 gathers outstanding
        float4 dA = sData[ja];
        float4 dC = sData[jc];
        int pA = __float_as_int(dA.w);
        int pC = __float_as_int(dC.w);
        const __half2* gbA = (const __half2*)&Wt_h[((pA & 63) << 6) + ob];
        const __half2* gaA = (const __half2*)&Wt_h[(((pA >> 6) & 63) << 6) + ob];
        const __half2* gbC = (const __half2*)&Wt_h[((pC & 63) << 6) + ob];
        const __half2* gaC = (const __half2*)&Wt_h[(((pC >> 6) & 63) << 6) + ob];
        __half2 hA0 = gbA[0], hA1 = gbA[1], hA2 = gaA[0], hA3 = gaA[1];
        __half2 hC0 = gbC[0], hC1 = gbC[1], hC2 = gaC[0], hC3 = gaC[1];

        float2 cA01 = __half22float2(__hadd2(hA0, hA2));
        float2 cA23 = __half22float2(__hadd2(hA1, hA3));
        float2 cC01 = __half22float2(__hadd2(hC0, hC2));
        float2 cC23 = __half22float2(__hadd2(hC1, hC3));

        float pbA = (pA & (1 << 12)) ? 1.0f : 0.0f;
        float fmA = (pA & (1 << 13)) ? 1.0f : 0.0f;
        float pbC = (pC & (1 << 12)) ? 1.0f : 0.0f;
        float fmC = (pC & (1 << 13)) ? 1.0f : 0.0f;

        float4 rA, rC;
        {
            float s;
            s = rowb.x + cA01.x; s = fmaf(pbA, w39v.x, s);
            s = fmaf(dA.x, w84v.x, s); s = fmaf(dA.y, w85v.x, s); s = fmaf(dA.z, w86v.x, s);
            rA.x = fmaf(fmA, s, bv.x);
            s = rowb.y + cA01.y; s = fmaf(pbA, w39v.y, s);
            s = fmaf(dA.x, w84v.y, s); s = fmaf(dA.y, w85v.y, s); s = fmaf(dA.z, w86v.y, s);
            rA.y = fmaf(fmA, s, bv.y);
            s = rowb.z + cA23.x; s = fmaf(pbA, w39v.z, s);
            s = fmaf(dA.x, w84v.z, s); s = fmaf(dA.y, w85v.z, s); s = fmaf(dA.z, w86v.z, s);
            rA.z = fmaf(fmA, s, bv.z);
            s = rowb.w + cA23.y; s = fmaf(pbA, w39v.w, s);
            s = fmaf(dA.x, w84v.w, s); s = fmaf(dA.y, w85v.w, s); s = fmaf(dA.z, w86v.w, s);
            rA.w = fmaf(fmA, s, bv.w);
        }
        *(float4*)&orow[(size_t)ja * NCH + ob] = rA;
        {
            float s;
            s = rowb.x + cC01.x; s = fmaf(pbC, w39v.x, s);
            s = fmaf(dC.x, w84v.x, s); s = fmaf(dC.y, w85v.x, s); s = fmaf(dC.z, w86v.x, s);
            rC.x = fmaf(fmC, s, bv.x);
            s = rowb.y + cC01.y; s = fmaf(pbC, w39v.y, s);
            s = fmaf(dC.x, w84v.y, s); s = fmaf(dC.y, w85v.y, s); s = fmaf(dC.z, w86v.y, s);
            rC.y = fmaf(fmC, s, bv.y);
            s = rowb.z + cC23.x; s = fmaf(pbC, w39v.z, s);
            s = fmaf(dC.x, w84v.z, s); s = fmaf(dC.y, w85v.z, s); s = fmaf(dC.z, w86v.z, s);
            rC.z = fmaf(fmC, s, bv.z);
            s = rowb.w + cC23.y; s = fmaf(pbC, w39v.w, s);
            s = fmaf(dC.x, w84v.w, s); s = fmaf(dC.y, w85v.w, s); s = fmaf(dC.z, w86v.w, s);
            rC.w = fmaf(fmC, s, bv.w);
        }
        *(float4*)&orow[(size_t)jc * NCH + ob] = rC;
    }
}

extern "C" void kernel_launch(void* const* d_in, const int* in_sizes, int n_in,
                              void* d_out, int out_size) {
    const float* pos    = (const float*)d_in[0];  // [4,768,37,3]
    const float* pb     = (const float*)d_in[1];  // [4,768,3]
    const float* pbmask = (const float*)d_in[2];  // [4,768]
    const float* aamask = (const float*)d_in[3];  // [4,768,37]
    const int*   aatype = (const int*)  d_in[4];  // [4,768]
    const float* lw     = (const float*)d_in[5];  // [64,88]
    const float* lb     = (const float*)d_in[6];  // [64]
    float* out = (float*)d_out;

    tpe_kernel<<<N_TEMPL * N_RES * JSPLIT, 256>>>(pos, pb, pbmask, aamask, aatype, lw, lb, out);
}

// round 7
// speedup vs baseline: 1.5993x; 1.5993x over previous
#include <cuda_runtime.h>
#include <cuda_fp16.h>
#include <cstdint>

#define N_TEMPL 4
#define N_RES   768
#define NCH     64
#define NGCOLS  62    // gather cols: 0..38 bins, 39 zero, 40..61 aa_j

// Prebuilt transposed tables (built once per launch by build_tables)
__device__ __half g_wt16[NGCOLS * NCH];   // fp16 gather table, col 39 zeroed
__device__ float  g_wt32[88 * NCH];       // fp32 transposed weights

__global__ void build_tables(const float* __restrict__ lw) {
    int idx = blockIdx.x * blockDim.x + threadIdx.x;   // < 88*64
    if (idx >= 88 * NCH) return;
    int c = idx >> 6, o = idx & 63;
    float v = lw[o * 88 + c];
    g_wt32[idx] = v;
    if (c < NGCOLS) g_wt16[idx] = __float2half_rn((c == 39) ? 0.0f : v);
}

// smem: Wt_h 7936 B + sData 768*16 = 12288 B + consts ≈ 20.4 KB
__global__ __launch_bounds__(256) void tpe_kernel(
    const float* __restrict__ pos,      // [T,768,37,3]
    const float* __restrict__ pb,       // [T,768,3]
    const float* __restrict__ pbm,      // [T,768]
    const float* __restrict__ aam,      // [T,768,37]
    const int*   __restrict__ aatype,   // [T,768]
    const float* __restrict__ lb,       // [64]
    float* __restrict__ out)            // [T,768,768,64]
{
    __shared__ alignas(16) __half Wt_h[NGCOLS * NCH];
    __shared__ float4 sData[N_RES];   // uvx, uvy, uvz, packed(bin | aaCol<<6 | pb<<12 | fm<<13)
    __shared__ float  sM[9];
    __shared__ float  sCa[3];
    __shared__ float  sPb[3];
    __shared__ float  sPbmI;
    __shared__ float  sFmI;
    __shared__ int    sAaI;

    const float EPS = 1e-6f;
    const int t = blockIdx.x / N_RES;
    const int i = blockIdx.x % N_RES;
    const int tid = threadIdx.x;

    // ---- Phase 0: coalesced linear copy of fp16 table + build rigid frame ----
    {
        const uint4* src = (const uint4*)g_wt16;     // 7936 B = 496 uint4
        uint4* dst = (uint4*)Wt_h;
        if (tid < 248) {
            dst[tid] = src[tid];
            dst[tid + 248] = src[tid + 248];
        }
    }

    if (tid == 0) {
        const float* pr = pos + ((size_t)(t * N_RES + i) * 37) * 3;
        float nx0 = pr[0], nx1 = pr[1], nx2 = pr[2];     // N
        float ca0 = pr[3], ca1 = pr[4], ca2 = pr[5];     // CA
        float cc0 = pr[6], cc1 = pr[7], cc2 = pr[8];     // C
        float n0 = nx0 - ca0, n1 = nx1 - ca1, n2 = nx2 - ca2;
        float c0 = cc0 - ca0, c1v = cc1 - ca1, c2v = cc2 - ca2;

        float d2xy = c0 * c0 + c1v * c1v;
        float norm1 = sqrtf(EPS + d2xy);
        float s1 = -c1v / norm1, co1 = c0 / norm1;
        float norm2 = sqrtf(EPS + d2xy + c2v * c2v);
        float s2 = c2v / norm2, co2 = sqrtf(d2xy) / norm2;

        float r00 = co2 * co1, r01 = -co2 * s1, r02 = s2;
        float r10 = s1,        r11 = co1,       r12 = 0.0f;
        float r20 = -s2 * co1, r21 = s2 * s1,   r22 = co2;

        float nyp = r10 * n0 + r11 * n1 + r12 * n2;
        float nzp = r20 * n0 + r21 * n1 + r22 * n2;
        float norm3 = sqrtf(EPS + nyp * nyp + nzp * nzp);
        float sn = -nzp / norm3, cn = nyp / norm3;

        sM[0] = r00; sM[1] = r01; sM[2] = r02;
        sM[3] = cn * r10 - sn * r20; sM[4] = cn * r11 - sn * r21; sM[5] = cn * r12 - sn * r22;
        sM[6] = sn * r10 + cn * r20; sM[7] = sn * r11 + cn * r21; sM[8] = sn * r12 + cn * r22;

        sCa[0] = ca0; sCa[1] = ca1; sCa[2] = ca2;
        const float* pbi = pb + (size_t)(t * N_RES + i) * 3;
        sPb[0] = pbi[0]; sPb[1] = pbi[1]; sPb[2] = pbi[2];
        sPbmI = pbm[t * N_RES + i];
        const float* ami = aam + (size_t)(t * N_RES + i) * 37;
        sFmI = ami[0] * ami[1] * ami[2];
        sAaI = aatype[t * N_RES + i];
    }
    __syncthreads();

    // ---------------- Phase 1: per-j scalars ----------------------------------
    {
        const float m0 = sM[0], m1 = sM[1], m2 = sM[2];
        const float m3 = sM[3], m4 = sM[4], m5 = sM[5];
        const float m6 = sM[6], m7 = sM[7], m8 = sM[8];
        const float cai0 = sCa[0], cai1 = sCa[1], cai2 = sCa[2];
        const float pbi0 = sPb[0], pbi1 = sPb[1], pbi2 = sPb[2];
        const float pbmi = sPbmI, fmi = sFmI;

        for (int j = tid; j < N_RES; j += 256) {
            // distogram bin (match reference FP ordering)
            const float* pbj = pb + (size_t)(t * N_RES + j) * 3;
            float dx = __fadd_rn(pbi0, -pbj[0]);
            float dy = __fadd_rn(pbi1, -pbj[1]);
            float dz = __fadd_rn(pbi2, -pbj[2]);
            float dsq = __fadd_rn(__fadd_rn(__fmul_rn(dx, dx), __fmul_rn(dy, dy)),
                                  __fmul_rn(dz, dz));
            int k = (int)floorf((sqrtf(dsq) - 3.25f) * 0.8f);
            k = min(max(k, -1), 38);
            int bin = -1;
            int clo = max(k - 1, 0), chi = min(k + 1, 38);
            #pragma unroll
            for (int c = 0; c < 3; ++c) {
                int cand = clo + c;
                if (cand > chi) break;
                float lbv = 3.25f + (float)cand * 1.25f;  lbv = lbv * lbv;
                float ubv = (cand == 38) ? 1e8f
                           : (3.25f + (float)(cand + 1) * 1.25f) *
                             (3.25f + (float)(cand + 1) * 1.25f);
                if (dsq > lbv && dsq < ubv) { bin = cand; break; }
            }

            // rigid vec + unit vector
            const float* pj = pos + ((size_t)(t * N_RES + j) * 37 + 1) * 3; // CA_j
            float ddx = pj[0] - cai0, ddy = pj[1] - cai1, ddz = pj[2] - cai2;
            float rvx = m0 * ddx + m1 * ddy + m2 * ddz;
            float rvy = m3 * ddx + m4 * ddy + m5 * ddz;
            float rvz = m6 * ddx + m7 * ddy + m8 * ddz;
            float inv = 1.0f / sqrtf(EPS + (rvx * rvx + rvy * rvy + rvz * rvz));
            float uvx = rvx * inv, uvy = rvy * inv, uvz = rvz * inv;

            const float* amj = aam + (size_t)(t * N_RES + j) * 37;
            float fm2 = fmi * (amj[0] * amj[1] * amj[2]);
            float pb2 = pbmi * pbm[t * N_RES + j];

            int binCol = (bin < 0) ? 39 : bin;
            int aaCol  = 40 + aatype[t * N_RES + j];
            int packed = binCol | (aaCol << 6);
            if (pb2 != 0.0f) packed |= 1 << 12;
            if (fm2 != 0.0f) packed |= 1 << 13;
            sData[j] = make_float4(uvx, uvy, uvz, __int_as_float(packed));
        }
    }
    __syncthreads();

    // ---------------- Phase 2: 16 ch-threads, 2 j's in flight per thread ------
    const int oq = tid & 15;
    const int jl = tid >> 4;          // 0..15
    const int ob = oq * 4;

    // Dense per-thread constants: coalesced float4 loads from prebuilt fp32 table
    float4 rowb, w39v, w84v, w85v, w86v, bv;
    {
        int ai = sAaI;
        float4 wai = *(const float4*)&g_wt32[(62 + ai) * NCH + ob];
        float4 w87 = *(const float4*)&g_wt32[87 * NCH + ob];
        rowb = make_float4(wai.x + w87.x, wai.y + w87.y, wai.z + w87.z, wai.w + w87.w);
        w39v = *(const float4*)&g_wt32[39 * NCH + ob];
        w84v = *(const float4*)&g_wt32[84 * NCH + ob];
        w85v = *(const float4*)&g_wt32[85 * NCH + ob];
        w86v = *(const float4*)&g_wt32[86 * NCH + ob];
        bv   = *(const float4*)&lb[ob];
    }

    float* orow = out + ((size_t)(t * N_RES + i) * N_RES) * NCH;

    #pragma unroll 3
    for (int jb = 0; jb < N_RES; jb += 32) {
        int ja = jb + jl;
        int jc = ja + 16;

        // issue all loads up front: 2 broadcasts + 4 gathers outstanding
        float4 dA = sData[ja];
        float4 dC = sData[jc];
        int pA = __float_as_int(dA.w);
        int pC = __float_as_int(dC.w);
        const __half2* gbA = (const __half2*)&Wt_h[((pA & 63) << 6) + ob];
        const __half2* gaA = (const __half2*)&Wt_h[(((pA >> 6) & 63) << 6) + ob];
        const __half2* gbC = (const __half2*)&Wt_h[((pC & 63) << 6) + ob];
        const __half2* gaC = (const __half2*)&Wt_h[(((pC >> 6) & 63) << 6) + ob];
        __half2 hA0 = gbA[0], hA1 = gbA[1], hA2 = gaA[0], hA3 = gaA[1];
        __half2 hC0 = gbC[0], hC1 = gbC[1], hC2 = gaC[0], hC3 = gaC[1];

        float2 cA01 = __half22float2(__hadd2(hA0, hA2));
        float2 cA23 = __half22float2(__hadd2(hA1, hA3));
        float2 cC01 = __half22float2(__hadd2(hC0, hC2));
        float2 cC23 = __half22float2(__hadd2(hC1, hC3));

        float pbA = (pA & (1 << 12)) ? 1.0f : 0.0f;
        float fmA = (pA & (1 << 13)) ? 1.0f : 0.0f;
        float pbC = (pC & (1 << 12)) ? 1.0f : 0.0f;
        float fmC = (pC & (1 << 13)) ? 1.0f : 0.0f;

        float4 rA, rC;
        {
            float s;
            s = rowb.x + cA01.x; s = fmaf(pbA, w39v.x, s);
            s = fmaf(dA.x, w84v.x, s); s = fmaf(dA.y, w85v.x, s); s = fmaf(dA.z, w86v.x, s);
            rA.x = fmaf(fmA, s, bv.x);
            s = rowb.y + cA01.y; s = fmaf(pbA, w39v.y, s);
            s = fmaf(dA.x, w84v.y, s); s = fmaf(dA.y, w85v.y, s); s = fmaf(dA.z, w86v.y, s);
            rA.y = fmaf(fmA, s, bv.y);
            s = rowb.z + cA23.x; s = fmaf(pbA, w39v.z, s);
            s = fmaf(dA.x, w84v.z, s); s = fmaf(dA.y, w85v.z, s); s = fmaf(dA.z, w86v.z, s);
            rA.z = fmaf(fmA, s, bv.z);
            s = rowb.w + cA23.y; s = fmaf(pbA, w39v.w, s);
            s = fmaf(dA.x, w84v.w, s); s = fmaf(dA.y, w85v.w, s); s = fmaf(dA.z, w86v.w, s);
            rA.w = fmaf(fmA, s, bv.w);
        }
        *(float4*)&orow[(size_t)ja * NCH + ob] = rA;
        {
            float s;
            s = rowb.x + cC01.x; s = fmaf(pbC, w39v.x, s);
            s = fmaf(dC.x, w84v.x, s); s = fmaf(dC.y, w85v.x, s); s = fmaf(dC.z, w86v.x, s);
            rC.x = fmaf(fmC, s, bv.x);
            s = rowb.y + cC01.y; s = fmaf(pbC, w39v.y, s);
            s = fmaf(dC.x, w84v.y, s); s = fmaf(dC.y, w85v.y, s); s = fmaf(dC.z, w86v.y, s);
            rC.y = fmaf(fmC, s, bv.y);
            s = rowb.z + cC23.x; s = fmaf(pbC, w39v.z, s);
            s = fmaf(dC.x, w84v.z, s); s = fmaf(dC.y, w85v.z, s); s = fmaf(dC.z, w86v.z, s);
            rC.z = fmaf(fmC, s, bv.z);
            s = rowb.w + cC23.y; s = fmaf(pbC, w39v.w, s);
            s = fmaf(dC.x, w84v.w, s); s = fmaf(dC.y, w85v.w, s); s = fmaf(dC.z, w86v.w, s);
            rC.w = fmaf(fmC, s, bv.w);
        }
        *(float4*)&orow[(size_t)jc * NCH + ob] = rC;
    }
}

extern "C" void kernel_launch(void* const* d_in, const int* in_sizes, int n_in,
                              void* d_out, int out_size) {
    const float* pos    = (const float*)d_in[0];  // [4,768,37,3]
    const float* pb     = (const float*)d_in[1];  // [4,768,3]
    const float* pbmask = (const float*)d_in[2];  // [4,768]
    const float* aamask = (const float*)d_in[3];  // [4,768,37]
    const int*   aatype = (const int*)  d_in[4];  // [4,768]
    const float* lw     = (const float*)d_in[5];  // [64,88]
    const float* lb     = (const float*)d_in[6];  // [64]
    float* out = (float*)d_out;

    build_tables<<<(88 * NCH + 255) / 256, 256>>>(lw);
    tpe_kernel<<<N_TEMPL * N_RES, 256>>>(pos, pb, pbmask, aamask, aatype, lb, out);
}

// round 8
// speedup vs baseline: 1.6719x; 1.0453x over previous
#include <cuda_runtime.h>
#include <cuda_fp16.h>
#include <cstdint>

#define N_TEMPL 4
#define N_RES   768
#define NCH     64
// fp16 gather table layout (102 columns):
//   cols 0..79  : (b,pb) pairs, col = 2*b+pb = (b<39 ? W[:,b] : 0) + pb*W[:,39]
//   cols 80..101: aa_j, col = 80+aa = W[:,40+aa]
#define NGCOLS  102

__device__ __half g_wt16[NGCOLS * NCH];
__device__ float  g_wt32[88 * NCH];       // fp32 transposed weights (dense consts)

__global__ void build_tables(const float* __restrict__ lw) {
    int idx = blockIdx.x * blockDim.x + threadIdx.x;   // < 102*64
    if (idx >= NGCOLS * NCH) return;
    int c = idx >> 6, o = idx & 63;
    if (c < 80) {
        int b = c >> 1, pbbit = c & 1;
        float v = (b < 39) ? lw[o * 88 + b] : 0.0f;
        if (pbbit) v += lw[o * 88 + 39];
        g_wt16[idx] = __float2half_rn(v);
    } else {
        g_wt16[idx] = __float2half_rn(lw[o * 88 + 40 + (c - 80)]);
    }
    // transpose full fp32 table (88 cols) using same thread range
    if (c < 88) g_wt32[c * NCH + o] = lw[o * 88 + c];
}

// smem: Wt_h 13056 B + sData 768*16 = 12288 B + consts ≈ 25.5 KB
__global__ __launch_bounds__(256, 5) void tpe_kernel(
    const float* __restrict__ pos,      // [T,768,37,3]
    const float* __restrict__ pb,       // [T,768,3]
    const float* __restrict__ pbm,      // [T,768]
    const float* __restrict__ aam,      // [T,768,37]
    const int*   __restrict__ aatype,   // [T,768]
    const float* __restrict__ lb,       // [64]
    float* __restrict__ out)            // [T,768,768,64]
{
    __shared__ alignas(16) __half Wt_h[NGCOLS * NCH];
    __shared__ float4 sData[N_RES];   // uvx, uvy, uvz, packed(bpCol | aaCol<<7 | fm<<14)
    __shared__ float  sM[9];
    __shared__ float  sCa[3];
    __shared__ float  sPb[3];
    __shared__ float  sPbmI;
    __shared__ float  sFmI;
    __shared__ int    sAaI;

    const float EPS = 1e-6f;
    const int t = blockIdx.x / N_RES;
    const int i = blockIdx.x % N_RES;
    const int tid = threadIdx.x;

    // ---- Phase 0: coalesced linear copy of fp16 table + build rigid frame ----
    {
        const uint4* src = (const uint4*)g_wt16;     // 13056 B = 816 uint4
        uint4* dst = (uint4*)Wt_h;
        #pragma unroll
        for (int idx = tid; idx < 816; idx += 256) dst[idx] = src[idx];
    }

    if (tid == 0) {
        const float* pr = pos + ((size_t)(t * N_RES + i) * 37) * 3;
        float nx0 = pr[0], nx1 = pr[1], nx2 = pr[2];     // N
        float ca0 = pr[3], ca1 = pr[4], ca2 = pr[5];     // CA
        float cc0 = pr[6], cc1 = pr[7], cc2 = pr[8];     // C
        float n0 = nx0 - ca0, n1 = nx1 - ca1, n2 = nx2 - ca2;
        float c0 = cc0 - ca0, c1v = cc1 - ca1, c2v = cc2 - ca2;

        float d2xy = c0 * c0 + c1v * c1v;
        float norm1 = sqrtf(EPS + d2xy);
        float s1 = -c1v / norm1, co1 = c0 / norm1;
        float norm2 = sqrtf(EPS + d2xy + c2v * c2v);
        float s2 = c2v / norm2, co2 = sqrtf(d2xy) / norm2;

        float r00 = co2 * co1, r01 = -co2 * s1, r02 = s2;
        float r10 = s1,        r11 = co1,       r12 = 0.0f;
        float r20 = -s2 * co1, r21 = s2 * s1,   r22 = co2;

        float nyp = r10 * n0 + r11 * n1 + r12 * n2;
        float nzp = r20 * n0 + r21 * n1 + r22 * n2;
        float norm3 = sqrtf(EPS + nyp * nyp + nzp * nzp);
        float sn = -nzp / norm3, cn = nyp / norm3;

        sM[0] = r00; sM[1] = r01; sM[2] = r02;
        sM[3] = cn * r10 - sn * r20; sM[4] = cn * r11 - sn * r21; sM[5] = cn * r12 - sn * r22;
        sM[6] = sn * r10 + cn * r20; sM[7] = sn * r11 + cn * r21; sM[8] = sn * r12 + cn * r22;

        sCa[0] = ca0; sCa[1] = ca1; sCa[2] = ca2;
        const float* pbi = pb + (size_t)(t * N_RES + i) * 3;
        sPb[0] = pbi[0]; sPb[1] = pbi[1]; sPb[2] = pbi[2];
        sPbmI = pbm[t * N_RES + i];
        const float* ami = aam + (size_t)(t * N_RES + i) * 37;
        sFmI = ami[0] * ami[1] * ami[2];
        sAaI = aatype[t * N_RES + i];
    }
    __syncthreads();

    // ---------------- Phase 1: per-j scalars ----------------------------------
    {
        const float m0 = sM[0], m1 = sM[1], m2 = sM[2];
        const float m3 = sM[3], m4 = sM[4], m5 = sM[5];
        const float m6 = sM[6], m7 = sM[7], m8 = sM[8];
        const float cai0 = sCa[0], cai1 = sCa[1], cai2 = sCa[2];
        const float pbi0 = sPb[0], pbi1 = sPb[1], pbi2 = sPb[2];
        const float pbmi = sPbmI, fmi = sFmI;

        for (int j = tid; j < N_RES; j += 256) {
            // distogram bin (match reference FP ordering)
            const float* pbj = pb + (size_t)(t * N_RES + j) * 3;
            float dx = __fadd_rn(pbi0, -pbj[0]);
            float dy = __fadd_rn(pbi1, -pbj[1]);
            float dz = __fadd_rn(pbi2, -pbj[2]);
            float dsq = __fadd_rn(__fadd_rn(__fmul_rn(dx, dx), __fmul_rn(dy, dy)),
                                  __fmul_rn(dz, dz));
            int k = (int)floorf((sqrtf(dsq) - 3.25f) * 0.8f);
            k = min(max(k, -1), 38);
            int bin = -1;
            int clo = max(k - 1, 0), chi = min(k + 1, 38);
            #pragma unroll
            for (int c = 0; c < 3; ++c) {
                int cand = clo + c;
                if (cand > chi) break;
                float lbv = 3.25f + (float)cand * 1.25f;  lbv = lbv * lbv;
                float ubv = (cand == 38) ? 1e8f
                           : (3.25f + (float)(cand + 1) * 1.25f) *
                             (3.25f + (float)(cand + 1) * 1.25f);
                if (dsq > lbv && dsq < ubv) { bin = cand; break; }
            }

            // rigid vec + unit vector
            const float* pj = pos + ((size_t)(t * N_RES + j) * 37 + 1) * 3; // CA_j
            float ddx = pj[0] - cai0, ddy = pj[1] - cai1, ddz = pj[2] - cai2;
            float rvx = m0 * ddx + m1 * ddy + m2 * ddz;
            float rvy = m3 * ddx + m4 * ddy + m5 * ddz;
            float rvz = m6 * ddx + m7 * ddy + m8 * ddz;
            float inv = 1.0f / sqrtf(EPS + (rvx * rvx + rvy * rvy + rvz * rvz));
            float uvx = rvx * inv, uvy = rvy * inv, uvz = rvz * inv;

            const float* amj = aam + (size_t)(t * N_RES + j) * 37;
            float fm2 = fmi * (amj[0] * amj[1] * amj[2]);
            float pb2 = pbmi * pbm[t * N_RES + j];

            int binCol = (bin < 0) ? 39 : bin;
            int bp = binCol * 2 + ((pb2 != 0.0f) ? 1 : 0);
            int aaCol = 80 + aatype[t * N_RES + j];
            int packed = bp | (aaCol << 7);
            if (fm2 != 0.0f) packed |= 1 << 14;
            sData[j] = make_float4(uvx, uvy, uvz, __int_as_float(packed));
        }
    }
    __syncthreads();

    // ---------------- Phase 2: 16 ch-threads, 2 j's in flight per thread ------
    const int oq = tid & 15;
    const int jl = tid >> 4;          // 0..15
    const int ob = oq * 4;

    // Dense per-thread constants: coalesced float4 loads from prebuilt fp32 table
    float4 rowb, w84v, w85v, w86v, bv;
    {
        int ai = sAaI;
        float4 wai = *(const float4*)&g_wt32[(62 + ai) * NCH + ob];
        float4 w87 = *(const float4*)&g_wt32[87 * NCH + ob];
        rowb = make_float4(wai.x + w87.x, wai.y + w87.y, wai.z + w87.z, wai.w + w87.w);
        w84v = *(const float4*)&g_wt32[84 * NCH + ob];
        w85v = *(const float4*)&g_wt32[85 * NCH + ob];
        w86v = *(const float4*)&g_wt32[86 * NCH + ob];
        bv   = *(const float4*)&lb[ob];
    }

    float* orow = out + ((size_t)(t * N_RES + i) * N_RES) * NCH;

    #pragma unroll 3
    for (int jb = 0; jb < N_RES; jb += 32) {
        int ja = jb + jl;
        int jc = ja + 16;

        // issue all loads up front: 2 broadcasts + 4 gathers outstanding
        float4 dA = sData[ja];
        float4 dC = sData[jc];
        int pA = __float_as_int(dA.w);
        int pC = __float_as_int(dC.w);
        const __half2* gbA = (const __half2*)&Wt_h[((pA & 127) << 6) + ob];
        const __half2* gaA = (const __half2*)&Wt_h[(((pA >> 7) & 127) << 6) + ob];
        const __half2* gbC = (const __half2*)&Wt_h[((pC & 127) << 6) + ob];
        const __half2* gaC = (const __half2*)&Wt_h[(((pC >> 7) & 127) << 6) + ob];
        __half2 hA0 = gbA[0], hA1 = gbA[1], hA2 = gaA[0], hA3 = gaA[1];
        __half2 hC0 = gbC[0], hC1 = gbC[1], hC2 = gaC[0], hC3 = gaC[1];

        float2 cA01 = __half22float2(__hadd2(hA0, hA2));
        float2 cA23 = __half22float2(__hadd2(hA1, hA3));
        float2 cC01 = __half22float2(__hadd2(hC0, hC2));
        float2 cC23 = __half22float2(__hadd2(hC1, hC3));

        float fmA = (pA & (1 << 14)) ? 1.0f : 0.0f;
        float fmC = (pC & (1 << 14)) ? 1.0f : 0.0f;

        float4 rA, rC;
        {
            float s;
            s = rowb.x + cA01.x;
            s = fmaf(dA.x, w84v.x, s); s = fmaf(dA.y, w85v.x, s); s = fmaf(dA.z, w86v.x, s);
            rA.x = fmaf(fmA, s, bv.x);
            s = rowb.y + cA01.y;
            s = fmaf(dA.x, w84v.y, s); s = fmaf(dA.y, w85v.y, s); s = fmaf(dA.z, w86v.y, s);
            rA.y = fmaf(fmA, s, bv.y);
            s = rowb.z + cA23.x;
            s = fmaf(dA.x, w84v.z, s); s = fmaf(dA.y, w85v.z, s); s = fmaf(dA.z, w86v.z, s);
            rA.z = fmaf(fmA, s, bv.z);
            s = rowb.w + cA23.y;
            s = fmaf(dA.x, w84v.w, s); s = fmaf(dA.y, w85v.w, s); s = fmaf(dA.z, w86v.w, s);
            rA.w = fmaf(fmA, s, bv.w);
        }
        *(float4*)&orow[(size_t)ja * NCH + ob] = rA;
        {
            float s;
            s = rowb.x + cC01.x;
            s = fmaf(dC.x, w84v.x, s); s = fmaf(dC.y, w85v.x, s); s = fmaf(dC.z, w86v.x, s);
            rC.x = fmaf(fmC, s, bv.x);
            s = rowb.y + cC01.y;
            s = fmaf(dC.x, w84v.y, s); s = fmaf(dC.y, w85v.y, s); s = fmaf(dC.z, w86v.y, s);
            rC.y = fmaf(fmC, s, bv.y);
            s = rowb.z + cC23.x;
            s = fmaf(dC.x, w84v.z, s); s = fmaf(dC.y, w85v.z, s); s = fmaf(dC.z, w86v.z, s);
            rC.z = fmaf(fmC, s, bv.z);
            s = rowb.w + cC23.y;
            s = fmaf(dC.x, w84v.w, s); s = fmaf(dC.y, w85v.w, s); s = fmaf(dC.z, w86v.w, s);
            rC.w = fmaf(fmC, s, bv.w);
        }
        *(float4*)&orow[(size_t)jc * NCH + ob] = rC;
    }
}

extern "C" void kernel_launch(void* const* d_in, const int* in_sizes, int n_in,
                              void* d_out, int out_size) {
    const float* pos    = (const float*)d_in[0];  // [4,768,37,3]
    const float* pb     = (const float*)d_in[1];  // [4,768,3]
    const float* pbmask = (const float*)d_in[2];  // [4,768]
    const float* aamask = (const float*)d_in[3];  // [4,768,37]
    const int*   aatype = (const int*)  d_in[4];  // [4,768]
    const float* lw     = (const float*)d_in[5];  // [64,88]
    const float* lb     = (const float*)d_in[6];  // [64]
    float* out = (float*)d_out;

    build_tables<<<(NGCOLS * NCH + 255) / 256, 256>>>(lw);
    tpe_kernel<<<N_TEMPL * N_RES, 256>>>(pos, pb, pbmask, aamask, aatype, lb, out);
}

// round 9
// speedup vs baseline: 2.0105x; 1.2025x over previous
#include <cuda_runtime.h>
#include <cuda_fp16.h>
#include <cstdint>

#define N_TEMPL 4
#define N_RES   768
#define NROWS   (N_TEMPL * N_RES)
#define NCH     64
// fp16 gather table layout (102 columns):
//   cols 0..79  : (b,pb) pairs, col = 2*b+pb = (b<39 ? W[:,b] : 0) + pb*W[:,39]
//   cols 80..101: aa_j, col = 80+aa = W[:,40+aa]
#define NGCOLS  102

__device__ __half g_wt16[NGCOLS * NCH];
__device__ float  g_wt32[88 * NCH];        // fp32 transposed weights (dense consts)
__device__ float4 g_jrec[2 * NROWS];       // per-(t,res): [ca.xyz, pb.x], [pb.yz, flags, 0]
__device__ float4 g_frame[3 * NROWS];      // per-(t,res): M row-major (9) + pad

__global__ void build_tables(const float* __restrict__ lw) {
    int idx = blockIdx.x * blockDim.x + threadIdx.x;   // < 102*64
    if (idx >= NGCOLS * NCH) return;
    int c = idx >> 6, o = idx & 63;
    if (c < 80) {
        int b = c >> 1, pbbit = c & 1;
        float v = (b < 39) ? lw[o * 88 + b] : 0.0f;
        if (pbbit) v += lw[o * 88 + 39];
        g_wt16[idx] = __float2half_rn(v);
    } else {
        g_wt16[idx] = __float2half_rn(lw[o * 88 + 40 + (c - 80)]);
    }
    if (c < 88) g_wt32[c * NCH + o] = lw[o * 88 + c];
}

__global__ void prep(const float* __restrict__ pos, const float* __restrict__ pb,
                     const float* __restrict__ pbm, const float* __restrict__ aam,
                     const int* __restrict__ aatype) {
    int idx = blockIdx.x * blockDim.x + threadIdx.x;   // < NROWS
    if (idx >= NROWS) return;
    const float EPS = 1e-6f;

    const float* pr = pos + (size_t)idx * 37 * 3;
    float nx0 = pr[0], nx1 = pr[1], nx2 = pr[2];     // N
    float ca0 = pr[3], ca1 = pr[4], ca2 = pr[5];     // CA
    float cc0 = pr[6], cc1 = pr[7], cc2 = pr[8];     // C

    const float* pbr = pb + (size_t)idx * 3;
    float pb0 = pbr[0], pb1 = pbr[1], pb2v = pbr[2];

    const float* amr = aam + (size_t)idx * 37;
    float fm = amr[0] * amr[1] * amr[2];
    float pm = pbm[idx];
    int aa = aatype[idx];
    int flags = aa;                      // bits 0..4: aa
    if (pm != 0.0f) flags |= 1 << 5;     // pbm bit
    if (fm != 0.0f) flags |= 1 << 6;     // frame-mask bit

    g_jrec[2 * idx]     = make_float4(ca0, ca1, ca2, pb0);
    g_jrec[2 * idx + 1] = make_float4(pb1, pb2v, __int_as_float(flags), 0.0f);

    // rigid frame M = nr @ c2 @ c1  (rigid_vec = M @ (ca_j - ca_i))
    float n0 = nx0 - ca0, n1 = nx1 - ca1, n2 = nx2 - ca2;
    float c0 = cc0 - ca0, c1v = cc1 - ca1, c2v = cc2 - ca2;
    float d2xy = c0 * c0 + c1v * c1v;
    float norm1 = sqrtf(EPS + d2xy);
    float s1 = -c1v / norm1, co1 = c0 / norm1;
    float norm2 = sqrtf(EPS + d2xy + c2v * c2v);
    float s2 = c2v / norm2, co2 = sqrtf(d2xy) / norm2;
    float r00 = co2 * co1, r01 = -co2 * s1, r02 = s2;
    float r10 = s1,        r11 = co1,       r12 = 0.0f;
    float r20 = -s2 * co1, r21 = s2 * s1,   r22 = co2;
    float nyp = r10 * n0 + r11 * n1 + r12 * n2;
    float nzp = r20 * n0 + r21 * n1 + r22 * n2;
    float norm3 = sqrtf(EPS + nyp * nyp + nzp * nzp);
    float sn = -nzp / norm3, cn = nyp / norm3;

    g_frame[3 * idx]     = make_float4(r00, r01, r02, cn * r10 - sn * r20);
    g_frame[3 * idx + 1] = make_float4(cn * r11 - sn * r21, cn * r12 - sn * r22,
                                       sn * r10 + cn * r20, sn * r11 + cn * r21);
    g_frame[3 * idx + 2] = make_float4(sn * r12 + cn * r22, 0.0f, 0.0f, 0.0f);
}

// smem: Wt_h 13056 B + sData 768*16 = 12288 B + consts ≈ 25.5 KB
__global__ __launch_bounds__(256, 5) void tpe_kernel(
    const float* __restrict__ lb,       // [64]
    float* __restrict__ out)            // [T,768,768,64]
{
    __shared__ alignas(16) __half Wt_h[NGCOLS * NCH];
    __shared__ float4 sData[N_RES];   // uvx, uvy, uvz, packed(bpCol | aaCol<<7 | fm<<14)
    __shared__ float4 sRow[5];        // frame (3) + jrec_i (2)

    const float EPS = 1e-6f;
    const int row = blockIdx.x;       // t*768 + i
    const int tid = threadIdx.x;

    // ---- Phase 0: coalesced table copy + row constants -----------------------
    {
        const uint4* src = (const uint4*)g_wt16;     // 13056 B = 816 uint4
        uint4* dst = (uint4*)Wt_h;
        #pragma unroll
        for (int idx = tid; idx < 816; idx += 256) dst[idx] = src[idx];
    }
    if (tid < 3) sRow[tid] = g_frame[3 * row + tid];
    else if (tid < 5) sRow[tid] = g_jrec[2 * row + (tid - 3)];
    __syncthreads();

    const float4 f0 = sRow[0], f1 = sRow[1], f2 = sRow[2];
    const float4 i0 = sRow[3], i1 = sRow[4];
    const int iflags = __float_as_int(i1.z);

    // ---------------- Phase 1: per-j scalars (2 coalesced float4 per j) -------
    {
        const float m0 = f0.x, m1 = f0.y, m2 = f0.z;
        const float m3 = f0.w, m4 = f1.x, m5 = f1.y;
        const float m6 = f1.z, m7 = f1.w, m8 = f2.x;
        const float cai0 = i0.x, cai1 = i0.y, cai2 = i0.z;
        const float pbi0 = i0.w, pbi1 = i1.x, pbi2 = i1.y;
        const int tbase = (row / N_RES) * N_RES;

        for (int j = tid; j < N_RES; j += 256) {
            float4 j0r = g_jrec[2 * (tbase + j)];
            float4 j1r = g_jrec[2 * (tbase + j) + 1];
            int jflags = __float_as_int(j1r.z);

            // distogram bin (match reference FP ordering)
            float dx = __fadd_rn(pbi0, -j0r.w);
            float dy = __fadd_rn(pbi1, -j1r.x);
            float dz = __fadd_rn(pbi2, -j1r.y);
            float dsq = __fadd_rn(__fadd_rn(__fmul_rn(dx, dx), __fmul_rn(dy, dy)),
                                  __fmul_rn(dz, dz));
            int k = (int)floorf((sqrtf(dsq) - 3.25f) * 0.8f);
            k = min(max(k, -1), 38);
            int bin = -1;
            int clo = max(k - 1, 0), chi = min(k + 1, 38);
            #pragma unroll
            for (int c = 0; c < 3; ++c) {
                int cand = clo + c;
                if (cand > chi) break;
                float lbv = 3.25f + (float)cand * 1.25f;  lbv = lbv * lbv;
                float ubv = (cand == 38) ? 1e8f
                           : (3.25f + (float)(cand + 1) * 1.25f) *
                             (3.25f + (float)(cand + 1) * 1.25f);
                if (dsq > lbv && dsq < ubv) { bin = cand; break; }
            }

            // rigid vec + unit vector
            float ddx = j0r.x - cai0, ddy = j0r.y - cai1, ddz = j0r.z - cai2;
            float rvx = m0 * ddx + m1 * ddy + m2 * ddz;
            float rvy = m3 * ddx + m4 * ddy + m5 * ddz;
            float rvz = m6 * ddx + m7 * ddy + m8 * ddz;
            float inv = 1.0f / sqrtf(EPS + (rvx * rvx + rvy * rvy + rvz * rvz));

            int binCol = (bin < 0) ? 39 : bin;
            int pbbit = ((iflags & jflags) >> 5) & 1;
            int bp = binCol * 2 + pbbit;
            int aaCol = 80 + (jflags & 31);
            int packed = bp | (aaCol << 7) | (((iflags & jflags) & (1 << 6)) << 8); // fm at bit 14
            sData[j] = make_float4(rvx * inv, rvy * inv, rvz * inv,
                                   __int_as_float(packed));
        }
    }
    __syncthreads();

    // ---------------- Phase 2: 16 ch-threads, 2 j's in flight per thread ------
    const int oq = tid & 15;
    const int jl = tid >> 4;          // 0..15
    const int ob = oq * 4;

    float4 rowb, w84v, w85v, w86v, bv;
    {
        int ai = iflags & 31;
        float4 wai = *(const float4*)&g_wt32[(62 + ai) * NCH + ob];
        float4 w87 = *(const float4*)&g_wt32[87 * NCH + ob];
        rowb = make_float4(wai.x + w87.x, wai.y + w87.y, wai.z + w87.z, wai.w + w87.w);
        w84v = *(const float4*)&g_wt32[84 * NCH + ob];
        w85v = *(const float4*)&g_wt32[85 * NCH + ob];
        w86v = *(const float4*)&g_wt32[86 * NCH + ob];
        bv   = *(const float4*)&lb[ob];
    }

    float* orow = out + (size_t)row * N_RES * NCH;

    #pragma unroll 3
    for (int jb = 0; jb < N_RES; jb += 32) {
        int ja = jb + jl;
        int jc = ja + 16;

        float4 dA = sData[ja];
        float4 dC = sData[jc];
        int pA = __float_as_int(dA.w);
        int pC = __float_as_int(dC.w);
        const __half2* gbA = (const __half2*)&Wt_h[((pA & 127) << 6) + ob];
        const __half2* gaA = (const __half2*)&Wt_h[(((pA >> 7) & 127) << 6) + ob];
        const __half2* gbC = (const __half2*)&Wt_h[((pC & 127) << 6) + ob];
        const __half2* gaC = (const __half2*)&Wt_h[(((pC >> 7) & 127) << 6) + ob];
        __half2 hA0 = gbA[0], hA1 = gbA[1], hA2 = gaA[0], hA3 = gaA[1];
        __half2 hC0 = gbC[0], hC1 = gbC[1], hC2 = gaC[0], hC3 = gaC[1];

        float2 cA01 = __half22float2(__hadd2(hA0, hA2));
        float2 cA23 = __half22float2(__hadd2(hA1, hA3));
        float2 cC01 = __half22float2(__hadd2(hC0, hC2));
        float2 cC23 = __half22float2(__hadd2(hC1, hC3));

        float fmA = (pA & (1 << 14)) ? 1.0f : 0.0f;
        float fmC = (pC & (1 << 14)) ? 1.0f : 0.0f;

        float4 rA, rC;
        {
            float s;
            s = rowb.x + cA01.x;
            s = fmaf(dA.x, w84v.x, s); s = fmaf(dA.y, w85v.x, s); s = fmaf(dA.z, w86v.x, s);
            rA.x = fmaf(fmA, s, bv.x);
            s = rowb.y + cA01.y;
            s = fmaf(dA.x, w84v.y, s); s = fmaf(dA.y, w85v.y, s); s = fmaf(dA.z, w86v.y, s);
            rA.y = fmaf(fmA, s, bv.y);
            s = rowb.z + cA23.x;
            s = fmaf(dA.x, w84v.z, s); s = fmaf(dA.y, w85v.z, s); s = fmaf(dA.z, w86v.z, s);
            rA.z = fmaf(fmA, s, bv.z);
            s = rowb.w + cA23.y;
            s = fmaf(dA.x, w84v.w, s); s = fmaf(dA.y, w85v.w, s); s = fmaf(dA.z, w86v.w, s);
            rA.w = fmaf(fmA, s, bv.w);
        }
        __stcs((float4*)&orow[(size_t)ja * NCH + ob], rA);
        {
            float s;
            s = rowb.x + cC01.x;
            s = fmaf(dC.x, w84v.x, s); s = fmaf(dC.y, w85v.x, s); s = fmaf(dC.z, w86v.x, s);
            rC.x = fmaf(fmC, s, bv.x);
            s = rowb.y + cC01.y;
            s = fmaf(dC.x, w84v.y, s); s = fmaf(dC.y, w85v.y, s); s = fmaf(dC.z, w86v.y, s);
            rC.y = fmaf(fmC, s, bv.y);
            s = rowb.z + cC23.x;
            s = fmaf(dC.x, w84v.z, s); s = fmaf(dC.y, w85v.z, s); s = fmaf(dC.z, w86v.z, s);
            rC.z = fmaf(fmC, s, bv.z);
            s = rowb.w + cC23.y;
            s = fmaf(dC.x, w84v.w, s); s = fmaf(dC.y, w85v.w, s); s = fmaf(dC.z, w86v.w, s);
            rC.w = fmaf(fmC, s, bv.w);
        }
        __stcs((float4*)&orow[(size_t)jc * NCH + ob], rC);
    }
}

extern "C" void kernel_launch(void* const* d_in, const int* in_sizes, int n_in,
                              void* d_out, int out_size) {
    const float* pos    = (const float*)d_in[0];  // [4,768,37,3]
    const float* pb     = (const float*)d_in[1];  // [4,768,3]
    const float* pbmask = (const float*)d_in[2];  // [4,768]
    const float* aamask = (const float*)d_in[3];  // [4,768,37]
    const int*   aatype = (const int*)  d_in[4];  // [4,768]
    const float* lw     = (const float*)d_in[5];  // [64,88]
    const float* lb     = (const float*)d_in[6];  // [64]
    float* out = (float*)d_out;

    build_tables<<<(NGCOLS * NCH + 255) / 256, 256>>>(lw);
    prep<<<(NROWS + 255) / 256, 256>>>(pos, pb, pbmask, aamask, aatype);
    tpe_kernel<<<NROWS, 256>>>(lb, out);
}

// round 10
// speedup vs baseline: 2.0561x; 1.0227x over previous
#include <cuda_runtime.h>
#include <cuda_fp16.h>
#include <cstdint>

#define N_TEMPL 4
#define N_RES   768
#define NROWS   (N_TEMPL * N_RES)
#define NCH     64
// fp16 gather table layout (102 columns):
//   cols 0..79  : (b,pb) pairs, col = 2*b+pb = (b<39 ? W[:,b] : 0) + pb*W[:,39]
//   cols 80..101: aa_j, col = 80+aa = W[:,40+aa]
#define NGCOLS  102
#define TBL_THREADS (NGCOLS * NCH)       // 6528

__device__ __half g_wt16[NGCOLS * NCH];
__device__ float  g_wt32[88 * NCH];        // fp32 transposed weights (dense consts)
__device__ float4 g_jrec[2 * NROWS];       // per-(t,res): [ca.xyz, pb.x], [pb.yz, flags, 0]
__device__ float4 g_frame[3 * NROWS];      // per-(t,res): M row-major (9) + pad

// Single fused prelaunch kernel: threads [0, 6528) build the weight tables,
// threads [6528, 6528+3072) build the per-row records/frames.
__global__ void prep_all(const float* __restrict__ lw,
                         const float* __restrict__ pos, const float* __restrict__ pb,
                         const float* __restrict__ pbm, const float* __restrict__ aam,
                         const int* __restrict__ aatype) {
    int gidx = blockIdx.x * blockDim.x + threadIdx.x;
    if (gidx < TBL_THREADS) {
        int c = gidx >> 6, o = gidx & 63;
        if (c < 80) {
            int b = c >> 1, pbbit = c & 1;
            float v = (b < 39) ? lw[o * 88 + b] : 0.0f;
            if (pbbit) v += lw[o * 88 + 39];
            g_wt16[gidx] = __float2half_rn(v);
        } else {
            g_wt16[gidx] = __float2half_rn(lw[o * 88 + 40 + (c - 80)]);
        }
        if (c < 88) g_wt32[c * NCH + o] = lw[o * 88 + c];
        return;
    }
    int idx = gidx - TBL_THREADS;
    if (idx >= NROWS) return;
    const float EPS = 1e-6f;

    const float* pr = pos + (size_t)idx * 37 * 3;
    float nx0 = pr[0], nx1 = pr[1], nx2 = pr[2];     // N
    float ca0 = pr[3], ca1 = pr[4], ca2 = pr[5];     // CA
    float cc0 = pr[6], cc1 = pr[7], cc2 = pr[8];     // C

    const float* pbr = pb + (size_t)idx * 3;
    float pb0 = pbr[0], pb1 = pbr[1], pb2v = pbr[2];

    const float* amr = aam + (size_t)idx * 37;
    float fm = amr[0] * amr[1] * amr[2];
    float pm = pbm[idx];
    int aa = aatype[idx];
    int flags = aa;                      // bits 0..4: aa
    if (pm != 0.0f) flags |= 1 << 5;     // pbm bit
    if (fm != 0.0f) flags |= 1 << 6;     // frame-mask bit

    g_jrec[2 * idx]     = make_float4(ca0, ca1, ca2, pb0);
    g_jrec[2 * idx + 1] = make_float4(pb1, pb2v, __int_as_float(flags), 0.0f);

    // rigid frame M = nr @ c2 @ c1  (rigid_vec = M @ (ca_j - ca_i))
    float n0 = nx0 - ca0, n1 = nx1 - ca1, n2 = nx2 - ca2;
    float c0 = cc0 - ca0, c1v = cc1 - ca1, c2v = cc2 - ca2;
    float d2xy = c0 * c0 + c1v * c1v;
    float norm1 = sqrtf(EPS + d2xy);
    float s1 = -c1v / norm1, co1 = c0 / norm1;
    float norm2 = sqrtf(EPS + d2xy + c2v * c2v);
    float s2 = c2v / norm2, co2 = sqrtf(d2xy) / norm2;
    float r00 = co2 * co1, r01 = -co2 * s1, r02 = s2;
    float r10 = s1,        r11 = co1,       r12 = 0.0f;
    float r20 = -s2 * co1, r21 = s2 * s1,   r22 = co2;
    float nyp = r10 * n0 + r11 * n1 + r12 * n2;
    float nzp = r20 * n0 + r21 * n1 + r22 * n2;
    float norm3 = sqrtf(EPS + nyp * nyp + nzp * nzp);
    float sn = -nzp / norm3, cn = nyp / norm3;

    g_frame[3 * idx]     = make_float4(r00, r01, r02, cn * r10 - sn * r20);
    g_frame[3 * idx + 1] = make_float4(cn * r11 - sn * r21, cn * r12 - sn * r22,
                                       sn * r10 + cn * r20, sn * r11 + cn * r21);
    g_frame[3 * idx + 2] = make_float4(sn * r12 + cn * r22, 0.0f, 0.0f, 0.0f);
}

// smem: Wt_h 13056 B + sData 768*16 = 12288 B + consts ≈ 25.5 KB
__global__ __launch_bounds__(256, 5) void tpe_kernel(
    const float* __restrict__ lb,       // [64]
    float* __restrict__ out)            // [T,768,768,64]
{
    __shared__ alignas(16) __half Wt_h[NGCOLS * NCH];
    __shared__ float4 sData[N_RES];   // uvx, uvy, uvz, packed(bpCol | aaCol<<7 | fm<<14)
    __shared__ float4 sRow[5];        // frame (3) + jrec_i (2)

    const float EPS = 1e-6f;
    const int row = blockIdx.x;       // t*768 + i
    const int tid = threadIdx.x;

    // ---- Phase 0: coalesced table copy + row constants -----------------------
    {
        const uint4* src = (const uint4*)g_wt16;     // 13056 B = 816 uint4
        uint4* dst = (uint4*)Wt_h;
        #pragma unroll
        for (int idx = tid; idx < 816; idx += 256) dst[idx] = src[idx];
    }
    if (tid < 3) sRow[tid] = g_frame[3 * row + tid];
    else if (tid < 5) sRow[tid] = g_jrec[2 * row + (tid - 3)];
    __syncthreads();

    const float4 f0 = sRow[0], f1 = sRow[1], f2 = sRow[2];
    const float4 i0 = sRow[3], i1 = sRow[4];
    const int iflags = __float_as_int(i1.z);

    // ---------------- Phase 1: per-j scalars (2 coalesced float4 per j) -------
    {
        const float m0 = f0.x, m1 = f0.y, m2 = f0.z;
        const float m3 = f0.w, m4 = f1.x, m5 = f1.y;
        const float m6 = f1.z, m7 = f1.w, m8 = f2.x;
        const float cai0 = i0.x, cai1 = i0.y, cai2 = i0.z;
        const float pbi0 = i0.w, pbi1 = i1.x, pbi2 = i1.y;
        const int tbase = (row / N_RES) * N_RES;

        for (int j = tid; j < N_RES; j += 256) {
            float4 j0r = g_jrec[2 * (tbase + j)];
            float4 j1r = g_jrec[2 * (tbase + j) + 1];
            int jflags = __float_as_int(j1r.z);

            // distogram bin (match reference FP ordering)
            float dx = __fadd_rn(pbi0, -j0r.w);
            float dy = __fadd_rn(pbi1, -j1r.x);
            float dz = __fadd_rn(pbi2, -j1r.y);
            float dsq = __fadd_rn(__fadd_rn(__fmul_rn(dx, dx), __fmul_rn(dy, dy)),
                                  __fmul_rn(dz, dz));
            int k = (int)floorf((sqrtf(dsq) - 3.25f) * 0.8f);
            k = min(max(k, -1), 38);
            int bin = -1;
            int clo = max(k - 1, 0), chi = min(k + 1, 38);
            #pragma unroll
            for (int c = 0; c < 3; ++c) {
                int cand = clo + c;
                if (cand > chi) break;
                float lbv = 3.25f + (float)cand * 1.25f;  lbv = lbv * lbv;
                float ubv = (cand == 38) ? 1e8f
                           : (3.25f + (float)(cand + 1) * 1.25f) *
                             (3.25f + (float)(cand + 1) * 1.25f);
                if (dsq > lbv && dsq < ubv) { bin = cand; break; }
            }

            // rigid vec + unit vector
            float ddx = j0r.x - cai0, ddy = j0r.y - cai1, ddz = j0r.z - cai2;
            float rvx = m0 * ddx + m1 * ddy + m2 * ddz;
            float rvy = m3 * ddx + m4 * ddy + m5 * ddz;
            float rvz = m6 * ddx + m7 * ddy + m8 * ddz;
            float inv = 1.0f / sqrtf(EPS + (rvx * rvx + rvy * rvy + rvz * rvz));

            int binCol = (bin < 0) ? 39 : bin;
            int pbbit = ((iflags & jflags) >> 5) & 1;
            int bp = binCol * 2 + pbbit;
            int aaCol = 80 + (jflags & 31);
            int packed = bp | (aaCol << 7) | (((iflags & jflags) & (1 << 6)) << 8); // fm at bit 14
            sData[j] = make_float4(rvx * inv, rvy * inv, rvz * inv,
                                   __int_as_float(packed));
        }
    }
    __syncthreads();

    // ---------------- Phase 2: 16 ch-threads, 2 j's in flight per thread ------
    const int oq = tid & 15;
    const int jl = tid >> 4;          // 0..15
    const int ob = oq * 4;

    float4 rowb, w84v, w85v, w86v, bv;
    {
        int ai = iflags & 31;
        float4 wai = *(const float4*)&g_wt32[(62 + ai) * NCH + ob];
        float4 w87 = *(const float4*)&g_wt32[87 * NCH + ob];
        rowb = make_float4(wai.x + w87.x, wai.y + w87.y, wai.z + w87.z, wai.w + w87.w);
        w84v = *(const float4*)&g_wt32[84 * NCH + ob];
        w85v = *(const float4*)&g_wt32[85 * NCH + ob];
        w86v = *(const float4*)&g_wt32[86 * NCH + ob];
        bv   = *(const float4*)&lb[ob];
    }

    float* orow = out + (size_t)row * N_RES * NCH;

    #pragma unroll 3
    for (int jb = 0; jb < N_RES; jb += 32) {
        int ja = jb + jl;
        int jc = ja + 16;

        float4 dA = sData[ja];
        float4 dC = sData[jc];
        int pA = __float_as_int(dA.w);
        int pC = __float_as_int(dC.w);
        const __half2* gbA = (const __half2*)&Wt_h[((pA & 127) << 6) + ob];
        const __half2* gaA = (const __half2*)&Wt_h[(((pA >> 7) & 127) << 6) + ob];
        const __half2* gbC = (const __half2*)&Wt_h[((pC & 127) << 6) + ob];
        const __half2* gaC = (const __half2*)&Wt_h[(((pC >> 7) & 127) << 6) + ob];
        __half2 hA0 = gbA[0], hA1 = gbA[1], hA2 = gaA[0], hA3 = gaA[1];
        __half2 hC0 = gbC[0], hC1 = gbC[1], hC2 = gaC[0], hC3 = gaC[1];

        float2 cA01 = __half22float2(__hadd2(hA0, hA2));
        float2 cA23 = __half22float2(__hadd2(hA1, hA3));
        float2 cC01 = __half22float2(__hadd2(hC0, hC2));
        float2 cC23 = __half22float2(__hadd2(hC1, hC3));

        float fmA = (pA & (1 << 14)) ? 1.0f : 0.0f;
        float fmC = (pC & (1 << 14)) ? 1.0f : 0.0f;

        float4 rA, rC;
        {
            float s;
            s = rowb.x + cA01.x;
            s = fmaf(dA.x, w84v.x, s); s = fmaf(dA.y, w85v.x, s); s = fmaf(dA.z, w86v.x, s);
            rA.x = fmaf(fmA, s, bv.x);
            s = rowb.y + cA01.y;
            s = fmaf(dA.x, w84v.y, s); s = fmaf(dA.y, w85v.y, s); s = fmaf(dA.z, w86v.y, s);
            rA.y = fmaf(fmA, s, bv.y);
            s = rowb.z + cA23.x;
            s = fmaf(dA.x, w84v.z, s); s = fmaf(dA.y, w85v.z, s); s = fmaf(dA.z, w86v.z, s);
            rA.z = fmaf(fmA, s, bv.z);
            s = rowb.w + cA23.y;
            s = fmaf(dA.x, w84v.w, s); s = fmaf(dA.y, w85v.w, s); s = fmaf(dA.z, w86v.w, s);
            rA.w = fmaf(fmA, s, bv.w);
        }
        __stcs((float4*)&orow[(size_t)ja * NCH + ob], rA);
        {
            float s;
            s = rowb.x + cC01.x;
            s = fmaf(dC.x, w84v.x, s); s = fmaf(dC.y, w85v.x, s); s = fmaf(dC.z, w86v.x, s);
            rC.x = fmaf(fmC, s, bv.x);
            s = rowb.y + cC01.y;
            s = fmaf(dC.x, w84v.y, s); s = fmaf(dC.y, w85v.y, s); s = fmaf(dC.z, w86v.y, s);
            rC.y = fmaf(fmC, s, bv.y);
            s = rowb.z + cC23.x;
            s = fmaf(dC.x, w84v.z, s); s = fmaf(dC.y, w85v.z, s); s = fmaf(dC.z, w86v.z, s);
            rC.z = fmaf(fmC, s, bv.z);
            s = rowb.w + cC23.y;
            s = fmaf(dC.x, w84v.w, s); s = fmaf(dC.y, w85v.w, s); s = fmaf(dC.z, w86v.w, s);
            rC.w = fmaf(fmC, s, bv.w);
        }
        __stcs((float4*)&orow[(size_t)jc * NCH + ob], rC);
    }
}

extern "C" void kernel_launch(void* const* d_in, const int* in_sizes, int n_in,
                              void* d_out, int out_size) {
    const float* pos    = (const float*)d_in[0];  // [4,768,37,3]
    const float* pb     = (const float*)d_in[1];  // [4,768,3]
    const float* pbmask = (const float*)d_in[2];  // [4,768]
    const float* aamask = (const float*)d_in[3];  // [4,768,37]
    const int*   aatype = (const int*)  d_in[4];  // [4,768]
    const float* lw     = (const float*)d_in[5];  // [64,88]
    const float* lb     = (const float*)d_in[6];  // [64]
    float* out = (float*)d_out;

    prep_all<<<(TBL_THREADS + NROWS + 255) / 256, 256>>>(lw, pos, pb, pbmask, aamask, aatype);
    tpe_kernel<<<NROWS, 256>>>(lb, out);
}

// round 11
// speedup vs baseline: 2.1017x; 1.0222x over previous
#include <cuda_runtime.h>
#include <cuda_fp16.h>
#include <cstdint>

#define N_TEMPL 4
#define N_RES   768
#define NROWS   (N_TEMPL * N_RES)
#define NCH     64
// fp16 gather table layout (102 columns):
//   cols 0..79  : (b,pb) pairs, col = 2*b+pb = (b<39 ? W[:,b] : 0) + pb*W[:,39]
//   cols 80..101: aa_j, col = 80+aa = W[:,40+aa]
#define NGCOLS  102
#define TBL_THREADS (NGCOLS * NCH)       // 6528

__device__ __half g_wt16[NGCOLS * NCH];
__device__ float  g_wt32[88 * NCH];        // fp32 transposed weights (dense consts)
__device__ float4 g_jrec[2 * NROWS];       // per-(t,res): [ca.xyz, pb.x], [pb.yz, flags, 0]
__device__ float4 g_frame[3 * NROWS];      // per-(t,res): M row-major (9) + pad

// Single fused prelaunch kernel: threads [0, 6528) build the weight tables,
// threads [6528, 6528+3072) build the per-row records/frames.
__global__ void prep_all(const float* __restrict__ lw,
                         const float* __restrict__ pos, const float* __restrict__ pb,
                         const float* __restrict__ pbm, const float* __restrict__ aam,
                         const int* __restrict__ aatype) {
    int gidx = blockIdx.x * blockDim.x + threadIdx.x;
    if (gidx < TBL_THREADS) {
        int c = gidx >> 6, o = gidx & 63;
        if (c < 80) {
            int b = c >> 1, pbbit = c & 1;
            float v = (b < 39) ? lw[o * 88 + b] : 0.0f;
            if (pbbit) v += lw[o * 88 + 39];
            g_wt16[gidx] = __float2half_rn(v);
        } else {
            g_wt16[gidx] = __float2half_rn(lw[o * 88 + 40 + (c - 80)]);
        }
        if (c < 88) g_wt32[c * NCH + o] = lw[o * 88 + c];
        return;
    }
    int idx = gidx - TBL_THREADS;
    if (idx >= NROWS) return;
    const float EPS = 1e-6f;

    const float* pr = pos + (size_t)idx * 37 * 3;
    float nx0 = pr[0], nx1 = pr[1], nx2 = pr[2];     // N
    float ca0 = pr[3], ca1 = pr[4], ca2 = pr[5];     // CA
    float cc0 = pr[6], cc1 = pr[7], cc2 = pr[8];     // C

    const float* pbr = pb + (size_t)idx * 3;
    float pb0 = pbr[0], pb1 = pbr[1], pb2v = pbr[2];

    const float* amr = aam + (size_t)idx * 37;
    float fm = amr[0] * amr[1] * amr[2];
    float pm = pbm[idx];
    int aa = aatype[idx];
    int flags = aa;                      // bits 0..4: aa
    if (pm != 0.0f) flags |= 1 << 5;     // pbm bit
    if (fm != 0.0f) flags |= 1 << 6;     // frame-mask bit

    g_jrec[2 * idx]     = make_float4(ca0, ca1, ca2, pb0);
    g_jrec[2 * idx + 1] = make_float4(pb1, pb2v, __int_as_float(flags), 0.0f);

    // rigid frame M = nr @ c2 @ c1  (rigid_vec = M @ (ca_j - ca_i))
    float n0 = nx0 - ca0, n1 = nx1 - ca1, n2 = nx2 - ca2;
    float c0 = cc0 - ca0, c1v = cc1 - ca1, c2v = cc2 - ca2;
    float d2xy = c0 * c0 + c1v * c1v;
    float norm1 = sqrtf(EPS + d2xy);
    float s1 = -c1v / norm1, co1 = c0 / norm1;
    float norm2 = sqrtf(EPS + d2xy + c2v * c2v);
    float s2 = c2v / norm2, co2 = sqrtf(d2xy) / norm2;
    float r00 = co2 * co1, r01 = -co2 * s1, r02 = s2;
    float r10 = s1,        r11 = co1,       r12 = 0.0f;
    float r20 = -s2 * co1, r21 = s2 * s1,   r22 = co2;
    float nyp = r10 * n0 + r11 * n1 + r12 * n2;
    float nzp = r20 * n0 + r21 * n1 + r22 * n2;
    float norm3 = sqrtf(EPS + nyp * nyp + nzp * nzp);
    float sn = -nzp / norm3, cn = nyp / norm3;

    g_frame[3 * idx]     = make_float4(r00, r01, r02, cn * r10 - sn * r20);
    g_frame[3 * idx + 1] = make_float4(cn * r11 - sn * r21, cn * r12 - sn * r22,
                                       sn * r10 + cn * r20, sn * r11 + cn * r21);
    g_frame[3 * idx + 2] = make_float4(sn * r12 + cn * r22, 0.0f, 0.0f, 0.0f);
}

// smem: Wt_h 13056 B + sData 768*16 = 12288 B + consts ≈ 25.5 KB (6 CTAs = 153 KB)
__global__ __launch_bounds__(256, 6) void tpe_kernel(
    const float* __restrict__ lb,       // [64]
    float* __restrict__ out)            // [T,768,768,64]
{
    __shared__ alignas(16) __half Wt_h[NGCOLS * NCH];
    __shared__ float4 sData[N_RES];   // uvx, uvy, uvz, packed(bpCol | aaCol<<7 | fm<<14)
    __shared__ float4 sRow[5];        // frame (3) + jrec_i (2)

    const float EPS = 1e-6f;
    const int row = blockIdx.x;       // t*768 + i
    const int tid = threadIdx.x;

    // ---- Phase 0: coalesced table copy + row constants -----------------------
    {
        const uint4* src = (const uint4*)g_wt16;     // 13056 B = 816 uint4
        uint4* dst = (uint4*)Wt_h;
        #pragma unroll
        for (int idx = tid; idx < 816; idx += 256) dst[idx] = src[idx];
    }
    if (tid < 3) sRow[tid] = g_frame[3 * row + tid];
    else if (tid < 5) sRow[tid] = g_jrec[2 * row + (tid - 3)];
    __syncthreads();

    const float4 i1 = sRow[4];
    const int iflags = __float_as_int(i1.z);

    // ---------------- Phase 1: per-j scalars (2 coalesced float4 per j) -------
    {
        const float4 f0 = sRow[0], f1 = sRow[1], f2 = sRow[2];
        const float4 i0 = sRow[3];
        const float m0 = f0.x, m1 = f0.y, m2 = f0.z;
        const float m3 = f0.w, m4 = f1.x, m5 = f1.y;
        const float m6 = f1.z, m7 = f1.w, m8 = f2.x;
        const float cai0 = i0.x, cai1 = i0.y, cai2 = i0.z;
        const float pbi0 = i0.w, pbi1 = i1.x, pbi2 = i1.y;
        const int tbase = (row / N_RES) * N_RES;

        for (int j = tid; j < N_RES; j += 256) {
            float4 j0r = g_jrec[2 * (tbase + j)];
            float4 j1r = g_jrec[2 * (tbase + j) + 1];
            int jflags = __float_as_int(j1r.z);

            // distogram bin (match reference FP ordering)
            float dx = __fadd_rn(pbi0, -j0r.w);
            float dy = __fadd_rn(pbi1, -j1r.x);
            float dz = __fadd_rn(pbi2, -j1r.y);
            float dsq = __fadd_rn(__fadd_rn(__fmul_rn(dx, dx), __fmul_rn(dy, dy)),
                                  __fmul_rn(dz, dz));
            int k = (int)floorf((sqrtf(dsq) - 3.25f) * 0.8f);
            k = min(max(k, -1), 38);
            int bin = -1;
            int clo = max(k - 1, 0), chi = min(k + 1, 38);
            #pragma unroll
            for (int c = 0; c < 3; ++c) {
                int cand = clo + c;
                if (cand > chi) break;
                float lbv = 3.25f + (float)cand * 1.25f;  lbv = lbv * lbv;
                float ubv = (cand == 38) ? 1e8f
                           : (3.25f + (float)(cand + 1) * 1.25f) *
                             (3.25f + (float)(cand + 1) * 1.25f);
                if (dsq > lbv && dsq < ubv) { bin = cand; break; }
            }

            // rigid vec + unit vector
            float ddx = j0r.x - cai0, ddy = j0r.y - cai1, ddz = j0r.z - cai2;
            float rvx = m0 * ddx + m1 * ddy + m2 * ddz;
            float rvy = m3 * ddx + m4 * ddy + m5 * ddz;
            float rvz = m6 * ddx + m7 * ddy + m8 * ddz;
            float inv = 1.0f / sqrtf(EPS + (rvx * rvx + rvy * rvy + rvz * rvz));

            int binCol = (bin < 0) ? 39 : bin;
            int pbbit = ((iflags & jflags) >> 5) & 1;
            int bp = binCol * 2 + pbbit;
            int aaCol = 80 + (jflags & 31);
            int packed = bp | (aaCol << 7) | (((iflags & jflags) & (1 << 6)) << 8); // fm at bit 14
            sData[j] = make_float4(rvx * inv, rvy * inv, rvz * inv,
                                   __int_as_float(packed));
        }
    }
    __syncthreads();

    // ---------------- Phase 2: 16 ch-threads, single j per iter (TLP mode) ----
    const int oq = tid & 15;
    const int jl = tid >> 4;          // 0..15
    const int ob = oq * 4;

    float4 rowb, w84v, w85v, w86v, bv;
    {
        int ai = iflags & 31;
        float4 wai = *(const float4*)&g_wt32[(62 + ai) * NCH + ob];
        float4 w87 = *(const float4*)&g_wt32[87 * NCH + ob];
        rowb = make_float4(wai.x + w87.x, wai.y + w87.y, wai.z + w87.z, wai.w + w87.w);
        w84v = *(const float4*)&g_wt32[84 * NCH + ob];
        w85v = *(const float4*)&g_wt32[85 * NCH + ob];
        w86v = *(const float4*)&g_wt32[86 * NCH + ob];
        bv   = *(const float4*)&lb[ob];
    }

    float* orow = out + (size_t)row * N_RES * NCH;

    #pragma unroll 2
    for (int jb = 0; jb < N_RES; jb += 16) {
        int j = jb + jl;

        float4 d = sData[j];
        int p = __float_as_int(d.w);
        const __half2* gb = (const __half2*)&Wt_h[((p & 127) << 6) + ob];
        const __half2* ga = (const __half2*)&Wt_h[(((p >> 7) & 127) << 6) + ob];
        __half2 h0 = gb[0], h1 = gb[1], h2 = ga[0], h3 = ga[1];

        float2 c01 = __half22float2(__hadd2(h0, h2));
        float2 c23 = __half22float2(__hadd2(h1, h3));
        float fm = (p & (1 << 14)) ? 1.0f : 0.0f;

        float4 r;
        {
            float s;
            s = rowb.x + c01.x;
            s = fmaf(d.x, w84v.x, s); s = fmaf(d.y, w85v.x, s); s = fmaf(d.z, w86v.x, s);
            r.x = fmaf(fm, s, bv.x);
            s = rowb.y + c01.y;
            s = fmaf(d.x, w84v.y, s); s = fmaf(d.y, w85v.y, s); s = fmaf(d.z, w86v.y, s);
            r.y = fmaf(fm, s, bv.y);
            s = rowb.z + c23.x;
            s = fmaf(d.x, w84v.z, s); s = fmaf(d.y, w85v.z, s); s = fmaf(d.z, w86v.z, s);
            r.z = fmaf(fm, s, bv.z);
            s = rowb.w + c23.y;
            s = fmaf(d.x, w84v.w, s); s = fmaf(d.y, w85v.w, s); s = fmaf(d.z, w86v.w, s);
            r.w = fmaf(fm, s, bv.w);
        }
        __stcs((float4*)&orow[(size_t)j * NCH + ob], r);
    }
}

extern "C" void kernel_launch(void* const* d_in, const int* in_sizes, int n_in,
                              void* d_out, int out_size) {
    const float* pos    = (const float*)d_in[0];  // [4,768,37,3]
    const float* pb     = (const float*)d_in[1];  // [4,768,3]
    const float* pbmask = (const float*)d_in[2];  // [4,768]
    const float* aamask = (const float*)d_in[3];  // [4,768,37]
    const int*   aatype = (const int*)  d_in[4];  // [4,768]
    const float* lw     = (const float*)d_in[5];  // [64,88]
    const float* lb     = (const float*)d_in[6];  // [64]
    float* out = (float*)d_out;

    prep_all<<<(TBL_THREADS + NROWS + 255) / 256, 256>>>(lw, pos, pb, pbmask, aamask, aatype);
    tpe_kernel<<<NROWS, 256>>>(lb, out);
}